// round 7
// baseline (speedup 1.0000x reference)
#include <cuda_runtime.h>

#define NN 100000
#define EE 1600000
#define IND 128
#define HIDD 64
#define NC 40

#define NBK 782               // ceil(NN / 128); 128 nodes per block, 256 threads
#define NTPB 256
#define EGRID 1184
#define ETPB 256
#define EWPB (ETPB / 32)
#define EWARPS (EGRID * EWPB)

typedef unsigned long long ull;

// ---------------- device scratch ----------------
__device__ float4 g_h0[NN * 16];     // embedding output
__device__ float4 g_h1[NN * 16];     // layer-0 accumulator (raw)
__device__ float4 g_hacc[NN * 16];   // layer-1 accumulator (raw)
__device__ float4 g_wh[NN * 16];
__device__ float  g_ssrc[NN];
__device__ float  g_sdst[NN];
__device__ float  g_pmax_s[NBK];
__device__ float  g_pmax_d[NBK];
__device__ float  g_psum[EGRID];
__device__ int    g_is64;
__device__ int2   g_epack[EE];

// ---------------- f32x2 helpers ----------------
__device__ __forceinline__ ull pk2(float a, float b) {
    ull r;
    asm("mov.b64 %0, {%1, %2};" : "=l"(r) : "f"(a), "f"(b));
    return r;
}
__device__ __forceinline__ ull dup2(float a) { return pk2(a, a); }
__device__ __forceinline__ float2 upk2(ull v) {
    float2 r;
    asm("mov.b64 {%0, %1}, %2;" : "=f"(r.x), "=f"(r.y) : "l"(v));
    return r;
}
__device__ __forceinline__ void ffma2(ull& acc, ull a, ull b) {
    asm("fma.rn.f32x2 %0, %1, %2, %0;" : "+l"(acc) : "l"(a), "l"(b));
}
__device__ __forceinline__ void red4(float* p, float a, float b, float c, float d) {
    asm volatile("red.global.add.v4.f32 [%0], {%1, %2, %3, %4};"
                 :: "l"(p), "f"(a), "f"(b), "f"(c), "f"(d) : "memory");
}
__device__ __forceinline__ float eluf(float x) { return x > 0.f ? x : (expf(x) - 1.f); }

// ---------------- dtype detect + index repack ----------------
__global__ void k_detect(const int* __restrict__ ei32) {
    int nz = 0;
    for (int i = threadIdx.x; i < 1024; i += blockDim.x)
        if (ei32[2 * i + 1] != 0) nz = 1;
    int cnt = __syncthreads_count(nz);
    if (threadIdx.x == 0) g_is64 = (cnt == 0) ? 1 : 0;
}

__global__ void k_prep(const void* __restrict__ ei_raw) {
    int e = blockIdx.x * blockDim.x + threadIdx.x;
    if (e >= EE) return;
    int s, d;
    if (g_is64) {
        s = (int)((const long long*)ei_raw)[e];
        d = (int)((const long long*)ei_raw)[EE + e];
    } else {
        s = ((const int*)ei_raw)[e];
        d = ((const int*)ei_raw)[EE + e];
    }
    s = min(max(s, 0), NN - 1);
    d = min(max(d, 0), NN - 1);
    g_epack[e] = make_int2(s, d);
}

// ---------------- embedding: h0 = x @ emb_w + emb_b ----------------
// 256 threads, 128 nodes/block: node = tid>>1 ; jh = tid&1 -> 32 output cols
__global__ void __launch_bounds__(NTPB, 3) k_emb(const float* __restrict__ x,
                                                 const float* __restrict__ w,
                                                 const float* __restrict__ b) {
    __shared__ float4 sW4[IND * HIDD / 4];   // 32 KB
    __shared__ float sb[HIDD];
    int tid = threadIdx.x;
    const float4* wg = reinterpret_cast<const float4*>(w);
    for (int i = tid; i < IND * HIDD / 4; i += NTPB) sW4[i] = wg[i];
    if (tid < HIDD) sb[tid] = b[tid];
    __syncthreads();

    int jh = tid & 1;
    int node = blockIdx.x * 128 + (tid >> 1);
    if (node >= NN) return;

    ull acc[16];
#pragma unroll
    for (int j = 0; j < 16; j++) acc[j] = pk2(sb[jh * 32 + 2 * j], sb[jh * 32 + 2 * j + 1]);

    const float4* xr = reinterpret_cast<const float4*>(x + (size_t)node * IND);
    const char* wbase = reinterpret_cast<const char*>(sW4) + jh * 128;

    float ha[4];
#pragma unroll 8
    for (int k = 0; k < IND; k++) {
        if ((k & 3) == 0) {
            float4 f = xr[k >> 2];
            ha[0] = f.x; ha[1] = f.y; ha[2] = f.z; ha[3] = f.w;
        }
        ull hp = dup2(ha[k & 3]);
        const ulonglong2* wrow = reinterpret_cast<const ulonglong2*>(wbase + k * (HIDD * 4));
#pragma unroll
        for (int j = 0; j < 8; j++) {
            ulonglong2 wv = wrow[j];
            ffma2(acc[2 * j], hp, wv.x);
            ffma2(acc[2 * j + 1], hp, wv.y);
        }
    }

    float4* o = g_h0 + (size_t)node * 16 + jh * 8;
#pragma unroll
    for (int q = 0; q < 8; q++) {
        float2 u = upk2(acc[2 * q]), v = upk2(acc[2 * q + 1]);
        o[q] = make_float4(u.x, u.y, v.x, v.y);
    }
}

// ---------------- per-layer GEMM + scores + zero-acc + block max ----------------
__global__ void __launch_bounds__(NTPB, 3) k_gemm_s(int layer,
                                                    const float* __restrict__ W,
                                                    const float* __restrict__ avec) {
    __shared__ float4 sW4[HIDD * HIDD / 4];  // 16 KB
    __shared__ float sa[2 * HIDD];
    __shared__ float sInv;
    int tid = threadIdx.x;
    const float4* wg = reinterpret_cast<const float4*>(W);
    for (int i = tid; i < HIDD * HIDD / 4; i += NTPB) sW4[i] = wg[i];
    if (tid < 2 * HIDD) sa[tid] = avec[tid];

    if (layer) {
        // redundant deterministic reduce of layer-0 softmax denominator
        float t = 0.0f;
        for (int i = tid; i < EGRID; i += NTPB) t += g_psum[i];
#pragma unroll
        for (int o = 16; o; o >>= 1) t += __shfl_xor_sync(0xffffffffu, t, o);
        __shared__ float sm[8];
        if ((tid & 31) == 0) sm[tid >> 5] = t;
        __syncthreads();
        if (tid == 0) {
            float s = 0.0f;
            for (int i = 0; i < 8; i++) s += sm[i];
            sInv = (s > 0.0f) ? (1.0f / s) : 0.0f;
        }
    }
    __syncthreads();
    float inv = layer ? sInv : 1.0f;

    int jh = tid & 1;
    int node = blockIdx.x * 128 + (tid >> 1);
    bool act = (node < NN);
    int nc = act ? node : 0;

    ull acc[16];
#pragma unroll
    for (int j = 0; j < 16; j++) acc[j] = 0ull;

    const float4* h = (layer ? g_h1 : g_h0) + (size_t)nc * 16;
    const char* wbase = reinterpret_cast<const char*>(sW4) + jh * 128;

    float ha[4];
#pragma unroll 8
    for (int k = 0; k < HIDD; k++) {
        if ((k & 3) == 0) {
            float4 f = h[k >> 2];
            if (layer) {
                f.x = eluf(f.x * inv); f.y = eluf(f.y * inv);
                f.z = eluf(f.z * inv); f.w = eluf(f.w * inv);
            }
            ha[0] = f.x; ha[1] = f.y; ha[2] = f.z; ha[3] = f.w;
        }
        ull hp = dup2(ha[k & 3]);
        const ulonglong2* wrow = reinterpret_cast<const ulonglong2*>(wbase + k * (HIDD * 4));
#pragma unroll
        for (int j = 0; j < 8; j++) {
            ulonglong2 wv = wrow[j];
            ffma2(acc[2 * j], hp, wv.x);
            ffma2(acc[2 * j + 1], hp, wv.y);
        }
    }

    // attention dots: partial over this thread's 32 columns, summed across jh pair
    float ssp = 0.f, sdp = 0.f;
#pragma unroll
    for (int j = 0; j < 16; j++) {
        float2 v = upk2(acc[j]);
        ssp += v.x * sa[jh * 32 + 2 * j] + v.y * sa[jh * 32 + 2 * j + 1];
        sdp += v.x * sa[HIDD + jh * 32 + 2 * j] + v.y * sa[HIDD + jh * 32 + 2 * j + 1];
    }
    float ss = ssp + __shfl_xor_sync(0xffffffffu, ssp, 1);
    float sd = sdp + __shfl_xor_sync(0xffffffffu, sdp, 1);

    if (act) {
        if (jh == 0) { g_ssrc[node] = ss; g_sdst[node] = sd; }
        float4* wout = g_wh + (size_t)node * 16 + jh * 8;
        float4* z = (layer ? g_hacc : g_h1) + (size_t)node * 16 + jh * 8;
        float4 zz = make_float4(0.f, 0.f, 0.f, 0.f);
#pragma unroll
        for (int q = 0; q < 8; q++) {
            float2 u = upk2(acc[2 * q]), v = upk2(acc[2 * q + 1]);
            wout[q] = make_float4(u.x, u.y, v.x, v.y);
            z[q] = zz;
        }
    }

    // block max partials
    float ms = act ? ss : -3.4e38f;
    float md = act ? sd : -3.4e38f;
#pragma unroll
    for (int o = 16; o; o >>= 1) {
        ms = fmaxf(ms, __shfl_xor_sync(0xffffffffu, ms, o));
        md = fmaxf(md, __shfl_xor_sync(0xffffffffu, md, o));
    }
    __shared__ float sms[8], smd[8];
    if ((tid & 31) == 0) { sms[tid >> 5] = ms; smd[tid >> 5] = md; }
    __syncthreads();
    if (tid == 0) {
        float a = sms[0], b = smd[0];
        for (int i = 1; i < 8; i++) { a = fmaxf(a, sms[i]); b = fmaxf(b, smd[i]); }
        g_pmax_s[blockIdx.x] = a;
        g_pmax_d[blockIdx.x] = b;
    }
}

// ---------------- fused edge pass ----------------
__global__ void __launch_bounds__(ETPB) k_edge(int acc_sel) {
    // redundant deterministic reduce of shift B
    __shared__ float sB;
    {
        float a = -3.4e38f, b = -3.4e38f;
        for (int i = threadIdx.x; i < NBK; i += ETPB) {
            a = fmaxf(a, g_pmax_s[i]);
            b = fmaxf(b, g_pmax_d[i]);
        }
#pragma unroll
        for (int o = 16; o; o >>= 1) {
            a = fmaxf(a, __shfl_xor_sync(0xffffffffu, a, o));
            b = fmaxf(b, __shfl_xor_sync(0xffffffffu, b, o));
        }
        __shared__ float ra[EWPB], rb[EWPB];
        if ((threadIdx.x & 31) == 0) { ra[threadIdx.x >> 5] = a; rb[threadIdx.x >> 5] = b; }
        __syncthreads();
        if (threadIdx.x == 0) {
            float ma = ra[0], mb = rb[0];
            for (int i = 1; i < EWPB; i++) { ma = fmaxf(ma, ra[i]); mb = fmaxf(mb, rb[i]); }
            sB = ma + mb;
        }
        __syncthreads();
    }
    const float B = sB;

    int lane = threadIdx.x & 31;
    int wid = threadIdx.x >> 5;
    int gw = blockIdx.x * EWPB + wid;

    const float* whf = reinterpret_cast<const float*>(g_wh);
    float* accf = reinterpret_cast<float*>(acc_sel ? g_hacc : g_h1);

    float psum = 0.0f;
    for (int base = gw * 32; base < EE; base += EWARPS * 32) {
        int e = base + lane;
        int sx = 0, sy = 0;
        float p = 0.0f;
        if (e < EE) {
            int2 sd = g_epack[e];
            sx = sd.x; sy = sd.y;
            float s = g_ssrc[sx] + g_sdst[sy];
            if (s > 0.0f) p = expf(s - B);
        }
        psum += p;

        unsigned actm = __ballot_sync(0xffffffffu, p != 0.0f);
        while (actm) {
            int j0 = __ffs(actm) - 1;
            actm &= actm - 1;
            int j1 = -1;
            if (actm) { j1 = __ffs(actm) - 1; actm &= actm - 1; }
            int j = (lane < 16) ? j0 : j1;
            int jj = (j < 0) ? 0 : j;
            int sj = __shfl_sync(0xffffffffu, sx, jj);
            int dj = __shfl_sync(0xffffffffu, sy, jj);
            float pj = __shfl_sync(0xffffffffu, p, jj);
            if (j >= 0) {
                int c = (lane & 15) * 4;
                const float4 wv = *reinterpret_cast<const float4*>(whf + (size_t)sj * HIDD + c);
                red4(accf + (size_t)dj * HIDD + c, pj * wv.x, pj * wv.y, pj * wv.z, pj * wv.w);
            }
        }
    }

#pragma unroll
    for (int o = 16; o; o >>= 1) psum += __shfl_xor_sync(0xffffffffu, psum, o);
    __shared__ float sm2[EWPB];
    if (lane == 0) sm2[wid] = psum;
    __syncthreads();
    if (threadIdx.x == 0) {
        float t = 0.0f;
        for (int i = 0; i < EWPB; i++) t += sm2[i];
        g_psum[blockIdx.x] = t;
    }
}

// ---------------- output head: transform + GEMM + ELU + log_softmax ----------------
__global__ void __launch_bounds__(NTPB, 4) k_out(const float* __restrict__ W,
                                                 const float* __restrict__ b,
                                                 float* __restrict__ out) {
    __shared__ __align__(16) float sW[HIDD * NC];   // 10 KB
    __shared__ float sb[NC];
    __shared__ float sInv;
    int tid = threadIdx.x;
    for (int i = tid; i < HIDD * NC; i += NTPB) sW[i] = W[i];
    if (tid < NC) sb[tid] = b[tid];
    {
        float t = 0.0f;
        for (int i = tid; i < EGRID; i += NTPB) t += g_psum[i];
#pragma unroll
        for (int o = 16; o; o >>= 1) t += __shfl_xor_sync(0xffffffffu, t, o);
        __shared__ float sm[8];
        if ((tid & 31) == 0) sm[tid >> 5] = t;
        __syncthreads();
        if (tid == 0) {
            float s = 0.0f;
            for (int i = 0; i < 8; i++) s += sm[i];
            sInv = (s > 0.0f) ? (1.0f / s) : 0.0f;
        }
    }
    __syncthreads();
    float inv = sInv;

    int jh = tid & 1;
    int node = blockIdx.x * 128 + (tid >> 1);
    if (node >= NN) return;

    ull acc[10];
#pragma unroll
    for (int j = 0; j < 10; j++) acc[j] = pk2(sb[jh * 20 + 2 * j], sb[jh * 20 + 2 * j + 1]);

    const float4* h = g_hacc + (size_t)node * 16;
    const char* wbase = reinterpret_cast<const char*>(sW) + jh * 80;

    float ha[4];
#pragma unroll 8
    for (int k = 0; k < HIDD; k++) {
        if ((k & 3) == 0) {
            float4 f = h[k >> 2];
            f.x = eluf(f.x * inv); f.y = eluf(f.y * inv);
            f.z = eluf(f.z * inv); f.w = eluf(f.w * inv);
            ha[0] = f.x; ha[1] = f.y; ha[2] = f.z; ha[3] = f.w;
        }
        ull hp = dup2(ha[k & 3]);
        const ulonglong2* wrow = reinterpret_cast<const ulonglong2*>(wbase + k * (NC * 4));
#pragma unroll
        for (int j = 0; j < 5; j++) {
            ulonglong2 wv = wrow[j];
            ffma2(acc[2 * j], hp, wv.x);
            ffma2(acc[2 * j + 1], hp, wv.y);
        }
    }

    float v[20];
#pragma unroll
    for (int j = 0; j < 10; j++) {
        float2 u = upk2(acc[j]);
        v[2 * j] = u.x;
        v[2 * j + 1] = u.y;
    }

    float m = -3.4e38f;
#pragma unroll
    for (int j = 0; j < 20; j++) {
        v[j] = (v[j] > 0.f) ? v[j] : (expf(v[j]) - 1.f);
        m = fmaxf(m, v[j]);
    }
    m = fmaxf(m, __shfl_xor_sync(0xffffffffu, m, 1));

    float se = 0.f;
#pragma unroll
    for (int j = 0; j < 20; j++) se += expf(v[j] - m);
    se += __shfl_xor_sync(0xffffffffu, se, 1);
    float lse = m + logf(se);

    float* o = out + (size_t)node * NC + jh * 20;
#pragma unroll
    for (int j = 0; j < 20; j++) o[j] = v[j] - lse;
}

// ---------------- launch ----------------
extern "C" void kernel_launch(void* const* d_in, const int* in_sizes, int n_in,
                              void* d_out, int out_size) {
    const float* x      = (const float*)d_in[0];
    const void*  ei     = (const void*)d_in[1];
    const float* emb_w  = (const float*)d_in[2];
    const float* emb_b  = (const float*)d_in[3];
    const float* Ws     = (const float*)d_in[4];
    const float* attn_a = (const float*)d_in[5];
    const float* out_w  = (const float*)d_in[6];
    const float* out_b  = (const float*)d_in[7];
    float* out          = (float*)d_out;

    (void)in_sizes; (void)n_in; (void)out_size;

    k_detect<<<1, 256>>>((const int*)ei);
    k_prep<<<(EE + 255) / 256, 256>>>(ei);
    k_emb<<<NBK, NTPB>>>(x, emb_w, emb_b);

    for (int l = 0; l < 2; l++) {
        k_gemm_s<<<NBK, NTPB>>>(l, Ws + l * HIDD * HIDD, attn_a + l * 2 * HIDD);
        k_edge<<<EGRID, ETPB>>>(l);
    }

    k_out<<<NBK, NTPB>>>(out_w, out_b, out);
}

// round 8
// speedup vs baseline: 1.2007x; 1.2007x over previous
#include <cuda_runtime.h>

#define NN 100000
#define EE 1600000
#define IND 128
#define HIDD 64
#define NC 40

#define NBG 391               // ceil(NN / 256); 256 nodes per block, 256 threads
#define NTPB 256
#define EGRID 1184
#define ETPB 256
#define EWPB (ETPB / 32)
#define EWARPS (EGRID * EWPB)

typedef unsigned long long ull;

// ---------------- device scratch ----------------
__device__ float4 g_h0[NN * 16];     // embedding output
__device__ float4 g_h1[NN * 16];     // layer-0 accumulator (raw)
__device__ float4 g_hacc[NN * 16];   // layer-1 accumulator (raw)
__device__ float4 g_wh[NN * 16];
__device__ float  g_ssrc[NN];
__device__ float  g_sdst[NN];
__device__ float  g_pmax_s[NBG];
__device__ float  g_pmax_d[NBG];
__device__ float  g_psum[EGRID];
__device__ int    g_is64;
__device__ int2   g_epack[EE];

// ---------------- f32x2 helpers ----------------
__device__ __forceinline__ ull pk2(float a, float b) {
    ull r;
    asm("mov.b64 %0, {%1, %2};" : "=l"(r) : "f"(a), "f"(b));
    return r;
}
__device__ __forceinline__ ull dup2(float a) { return pk2(a, a); }
__device__ __forceinline__ float2 upk2(ull v) {
    float2 r;
    asm("mov.b64 {%0, %1}, %2;" : "=f"(r.x), "=f"(r.y) : "l"(v));
    return r;
}
__device__ __forceinline__ void ffma2(ull& acc, ull a, ull b) {
    asm("fma.rn.f32x2 %0, %1, %2, %0;" : "+l"(acc) : "l"(a), "l"(b));
}
__device__ __forceinline__ void red4(float* p, float a, float b, float c, float d) {
    asm volatile("red.global.add.v4.f32 [%0], {%1, %2, %3, %4};"
                 :: "l"(p), "f"(a), "f"(b), "f"(c), "f"(d) : "memory");
}
__device__ __forceinline__ float eluf(float x) { return x > 0.f ? x : (expf(x) - 1.f); }

// ---------------- dtype detect + index repack ----------------
__global__ void k_detect(const int* __restrict__ ei32) {
    int nz = 0;
    for (int i = threadIdx.x; i < 1024; i += blockDim.x)
        if (ei32[2 * i + 1] != 0) nz = 1;
    int cnt = __syncthreads_count(nz);
    if (threadIdx.x == 0) g_is64 = (cnt == 0) ? 1 : 0;
}

__global__ void k_prep(const void* __restrict__ ei_raw) {
    int e = blockIdx.x * blockDim.x + threadIdx.x;
    if (e >= EE) return;
    int s, d;
    if (g_is64) {
        s = (int)((const long long*)ei_raw)[e];
        d = (int)((const long long*)ei_raw)[EE + e];
    } else {
        s = ((const int*)ei_raw)[e];
        d = ((const int*)ei_raw)[EE + e];
    }
    s = min(max(s, 0), NN - 1);
    d = min(max(d, 0), NN - 1);
    g_epack[e] = make_int2(s, d);
}

// ---------------- embedding: h0 = x @ emb_w + emb_b ----------------
// 256 threads, 256 nodes/block: jq = tid&3 (16-col quarter), 4 nodes per thread
__global__ void __launch_bounds__(NTPB, 2) k_emb(const float* __restrict__ x,
                                                 const float* __restrict__ w,
                                                 const float* __restrict__ b) {
    __shared__ float4 sW4[IND * HIDD / 4];   // 32 KB
    __shared__ float sb[HIDD];
    int tid = threadIdx.x;
    const float4* wg = reinterpret_cast<const float4*>(w);
    for (int i = tid; i < IND * HIDD / 4; i += NTPB) sW4[i] = wg[i];
    if (tid < HIDD) sb[tid] = b[tid];
    __syncthreads();

    int jq = tid & 3;
    int n0 = blockIdx.x * 256 + (tid >> 2) * 4;
    bool av[4]; int nn[4];
#pragma unroll
    for (int i = 0; i < 4; i++) {
        int n = n0 + i;
        av[i] = (n < NN);
        nn[i] = av[i] ? n : 0;
    }

    ull acc[4][8];
#pragma unroll
    for (int i = 0; i < 4; i++)
#pragma unroll
        for (int j = 0; j < 8; j++)
            acc[i][j] = pk2(sb[jq * 16 + 2 * j], sb[jq * 16 + 2 * j + 1]);

    const char* wbase = reinterpret_cast<const char*>(sW4) + jq * 64;

    for (int k4 = 0; k4 < IND / 4; k4++) {
        float4 f[4];
#pragma unroll
        for (int i = 0; i < 4; i++)
            f[i] = reinterpret_cast<const float4*>(x + (size_t)nn[i] * IND)[k4];
#pragma unroll
        for (int q = 0; q < 4; q++) {
            ull hp[4];
            hp[0] = dup2(q == 0 ? f[0].x : q == 1 ? f[0].y : q == 2 ? f[0].z : f[0].w);
            hp[1] = dup2(q == 0 ? f[1].x : q == 1 ? f[1].y : q == 2 ? f[1].z : f[1].w);
            hp[2] = dup2(q == 0 ? f[2].x : q == 1 ? f[2].y : q == 2 ? f[2].z : f[2].w);
            hp[3] = dup2(q == 0 ? f[3].x : q == 1 ? f[3].y : q == 2 ? f[3].z : f[3].w);
            const ulonglong2* wrow =
                reinterpret_cast<const ulonglong2*>(wbase + (k4 * 4 + q) * (HIDD * 4));
#pragma unroll
            for (int j4 = 0; j4 < 4; j4++) {
                ulonglong2 wv = wrow[j4];
#pragma unroll
                for (int i = 0; i < 4; i++) {
                    ffma2(acc[i][2 * j4], hp[i], wv.x);
                    ffma2(acc[i][2 * j4 + 1], hp[i], wv.y);
                }
            }
        }
    }

#pragma unroll
    for (int i = 0; i < 4; i++) {
        if (!av[i]) continue;
        float4* o = g_h0 + (size_t)nn[i] * 16 + jq * 4;
#pragma unroll
        for (int q = 0; q < 4; q++) {
            float2 u = upk2(acc[i][2 * q]), v = upk2(acc[i][2 * q + 1]);
            o[q] = make_float4(u.x, u.y, v.x, v.y);
        }
    }
}

// ---------------- per-layer GEMM + scores + zero-acc + block max ----------------
__global__ void __launch_bounds__(NTPB, 2) k_gemm_s(int layer,
                                                    const float* __restrict__ W,
                                                    const float* __restrict__ avec) {
    __shared__ float4 sW4[HIDD * HIDD / 4];  // 16 KB
    __shared__ float sa[2 * HIDD];
    __shared__ float sInv;
    int tid = threadIdx.x;
    const float4* wg = reinterpret_cast<const float4*>(W);
    for (int i = tid; i < HIDD * HIDD / 4; i += NTPB) sW4[i] = wg[i];
    if (tid < 2 * HIDD) sa[tid] = avec[tid];

    if (layer) {
        float t = 0.0f;
        for (int i = tid; i < EGRID; i += NTPB) t += g_psum[i];
#pragma unroll
        for (int o = 16; o; o >>= 1) t += __shfl_xor_sync(0xffffffffu, t, o);
        __shared__ float sm[8];
        if ((tid & 31) == 0) sm[tid >> 5] = t;
        __syncthreads();
        if (tid == 0) {
            float s = 0.0f;
            for (int i = 0; i < 8; i++) s += sm[i];
            sInv = (s > 0.0f) ? (1.0f / s) : 0.0f;
        }
    }
    __syncthreads();
    float inv = layer ? sInv : 1.0f;

    int jq = tid & 3;
    int n0 = blockIdx.x * 256 + (tid >> 2) * 4;
    bool av[4]; int nn[4];
#pragma unroll
    for (int i = 0; i < 4; i++) {
        int n = n0 + i;
        av[i] = (n < NN);
        nn[i] = av[i] ? n : 0;
    }

    ull acc[4][8];
#pragma unroll
    for (int i = 0; i < 4; i++)
#pragma unroll
        for (int j = 0; j < 8; j++) acc[i][j] = 0ull;

    const float4* hb = layer ? g_h1 : g_h0;
    const char* wbase = reinterpret_cast<const char*>(sW4) + jq * 64;

    for (int k4 = 0; k4 < HIDD / 4; k4++) {
        float4 f[4];
#pragma unroll
        for (int i = 0; i < 4; i++) {
            float4 t = hb[(size_t)nn[i] * 16 + k4];
            if (layer) {
                t.x = eluf(t.x * inv); t.y = eluf(t.y * inv);
                t.z = eluf(t.z * inv); t.w = eluf(t.w * inv);
            }
            f[i] = t;
        }
#pragma unroll
        for (int q = 0; q < 4; q++) {
            ull hp[4];
            hp[0] = dup2(q == 0 ? f[0].x : q == 1 ? f[0].y : q == 2 ? f[0].z : f[0].w);
            hp[1] = dup2(q == 0 ? f[1].x : q == 1 ? f[1].y : q == 2 ? f[1].z : f[1].w);
            hp[2] = dup2(q == 0 ? f[2].x : q == 1 ? f[2].y : q == 2 ? f[2].z : f[2].w);
            hp[3] = dup2(q == 0 ? f[3].x : q == 1 ? f[3].y : q == 2 ? f[3].z : f[3].w);
            const ulonglong2* wrow =
                reinterpret_cast<const ulonglong2*>(wbase + (k4 * 4 + q) * (HIDD * 4));
#pragma unroll
            for (int j4 = 0; j4 < 4; j4++) {
                ulonglong2 wv = wrow[j4];
#pragma unroll
                for (int i = 0; i < 4; i++) {
                    ffma2(acc[i][2 * j4], hp[i], wv.x);
                    ffma2(acc[i][2 * j4 + 1], hp[i], wv.y);
                }
            }
        }
    }

    // attention dots: partial over 16 cols, butterfly over 4-lane quarter group
    float ss[4], sd[4];
#pragma unroll
    for (int i = 0; i < 4; i++) {
        float s1 = 0.f, s2 = 0.f;
#pragma unroll
        for (int j = 0; j < 8; j++) {
            float2 v = upk2(acc[i][j]);
            s1 += v.x * sa[jq * 16 + 2 * j] + v.y * sa[jq * 16 + 2 * j + 1];
            s2 += v.x * sa[HIDD + jq * 16 + 2 * j] + v.y * sa[HIDD + jq * 16 + 2 * j + 1];
        }
        s1 += __shfl_xor_sync(0xffffffffu, s1, 1);
        s1 += __shfl_xor_sync(0xffffffffu, s1, 2);
        s2 += __shfl_xor_sync(0xffffffffu, s2, 1);
        s2 += __shfl_xor_sync(0xffffffffu, s2, 2);
        ss[i] = s1; sd[i] = s2;
    }

    float4* zb = layer ? g_hacc : g_h1;
    float4 zz = make_float4(0.f, 0.f, 0.f, 0.f);
#pragma unroll
    for (int i = 0; i < 4; i++) {
        if (!av[i]) continue;
        if (jq == 0) { g_ssrc[nn[i]] = ss[i]; g_sdst[nn[i]] = sd[i]; }
        float4* wout = g_wh + (size_t)nn[i] * 16 + jq * 4;
        float4* z = zb + (size_t)nn[i] * 16 + jq * 4;
#pragma unroll
        for (int q = 0; q < 4; q++) {
            float2 u = upk2(acc[i][2 * q]), v = upk2(acc[i][2 * q + 1]);
            wout[q] = make_float4(u.x, u.y, v.x, v.y);
            z[q] = zz;
        }
    }

    // block max partials
    float ms = -3.4e38f, md = -3.4e38f;
#pragma unroll
    for (int i = 0; i < 4; i++) {
        if (av[i]) { ms = fmaxf(ms, ss[i]); md = fmaxf(md, sd[i]); }
    }
#pragma unroll
    for (int o = 16; o; o >>= 1) {
        ms = fmaxf(ms, __shfl_xor_sync(0xffffffffu, ms, o));
        md = fmaxf(md, __shfl_xor_sync(0xffffffffu, md, o));
    }
    __shared__ float sms[8], smd[8];
    if ((tid & 31) == 0) { sms[tid >> 5] = ms; smd[tid >> 5] = md; }
    __syncthreads();
    if (tid == 0) {
        float a = sms[0], b = smd[0];
        for (int i = 1; i < 8; i++) { a = fmaxf(a, sms[i]); b = fmaxf(b, smd[i]); }
        g_pmax_s[blockIdx.x] = a;
        g_pmax_d[blockIdx.x] = b;
    }
}

// ---------------- fused edge pass ----------------
__global__ void __launch_bounds__(ETPB) k_edge(int acc_sel) {
    __shared__ float sB;
    {
        float a = -3.4e38f, b = -3.4e38f;
        for (int i = threadIdx.x; i < NBG; i += ETPB) {
            a = fmaxf(a, g_pmax_s[i]);
            b = fmaxf(b, g_pmax_d[i]);
        }
#pragma unroll
        for (int o = 16; o; o >>= 1) {
            a = fmaxf(a, __shfl_xor_sync(0xffffffffu, a, o));
            b = fmaxf(b, __shfl_xor_sync(0xffffffffu, b, o));
        }
        __shared__ float ra[EWPB], rb[EWPB];
        if ((threadIdx.x & 31) == 0) { ra[threadIdx.x >> 5] = a; rb[threadIdx.x >> 5] = b; }
        __syncthreads();
        if (threadIdx.x == 0) {
            float ma = ra[0], mb = rb[0];
            for (int i = 1; i < EWPB; i++) { ma = fmaxf(ma, ra[i]); mb = fmaxf(mb, rb[i]); }
            sB = ma + mb;
        }
        __syncthreads();
    }
    const float B = sB;

    int lane = threadIdx.x & 31;
    int wid = threadIdx.x >> 5;
    int gw = blockIdx.x * EWPB + wid;

    const float* whf = reinterpret_cast<const float*>(g_wh);
    float* accf = reinterpret_cast<float*>(acc_sel ? g_hacc : g_h1);

    float psum = 0.0f;
    for (int base = gw * 32; base < EE; base += EWARPS * 32) {
        int e = base + lane;
        int sx = 0, sy = 0;
        float p = 0.0f;
        if (e < EE) {
            int2 sd = g_epack[e];
            sx = sd.x; sy = sd.y;
            float s = g_ssrc[sx] + g_sdst[sy];
            if (s > 0.0f) p = expf(s - B);
        }
        psum += p;

        unsigned actm = __ballot_sync(0xffffffffu, p != 0.0f);
        while (actm) {
            int j0 = __ffs(actm) - 1;
            actm &= actm - 1;
            int j1 = -1;
            if (actm) { j1 = __ffs(actm) - 1; actm &= actm - 1; }
            int j = (lane < 16) ? j0 : j1;
            int jj = (j < 0) ? 0 : j;
            int sj = __shfl_sync(0xffffffffu, sx, jj);
            int dj = __shfl_sync(0xffffffffu, sy, jj);
            float pj = __shfl_sync(0xffffffffu, p, jj);
            if (j >= 0) {
                int c = (lane & 15) * 4;
                const float4 wv = *reinterpret_cast<const float4*>(whf + (size_t)sj * HIDD + c);
                red4(accf + (size_t)dj * HIDD + c, pj * wv.x, pj * wv.y, pj * wv.z, pj * wv.w);
            }
        }
    }

#pragma unroll
    for (int o = 16; o; o >>= 1) psum += __shfl_xor_sync(0xffffffffu, psum, o);
    __shared__ float sm2[EWPB];
    if (lane == 0) sm2[wid] = psum;
    __syncthreads();
    if (threadIdx.x == 0) {
        float t = 0.0f;
        for (int i = 0; i < EWPB; i++) t += sm2[i];
        g_psum[blockIdx.x] = t;
    }
}

// ---------------- output head: transform + GEMM + ELU + log_softmax ----------------
__global__ void __launch_bounds__(NTPB, 2) k_out(const float* __restrict__ W,
                                                 const float* __restrict__ b,
                                                 float* __restrict__ out) {
    __shared__ __align__(16) float sW[HIDD * NC];   // 10 KB
    __shared__ float sb[NC];
    __shared__ float sInv;
    int tid = threadIdx.x;
    for (int i = tid; i < HIDD * NC; i += NTPB) sW[i] = W[i];
    if (tid < NC) sb[tid] = b[tid];
    {
        float t = 0.0f;
        for (int i = tid; i < EGRID; i += NTPB) t += g_psum[i];
#pragma unroll
        for (int o = 16; o; o >>= 1) t += __shfl_xor_sync(0xffffffffu, t, o);
        __shared__ float sm[8];
        if ((tid & 31) == 0) sm[tid >> 5] = t;
        __syncthreads();
        if (tid == 0) {
            float s = 0.0f;
            for (int i = 0; i < 8; i++) s += sm[i];
            sInv = (s > 0.0f) ? (1.0f / s) : 0.0f;
        }
    }
    __syncthreads();
    float inv = sInv;

    int jq = tid & 3;
    int n0 = blockIdx.x * 256 + (tid >> 2) * 4;
    bool av[4]; int nn[4];
#pragma unroll
    for (int i = 0; i < 4; i++) {
        int n = n0 + i;
        av[i] = (n < NN);
        nn[i] = av[i] ? n : 0;
    }

    ull acc[4][5];
#pragma unroll
    for (int i = 0; i < 4; i++)
#pragma unroll
        for (int j = 0; j < 5; j++)
            acc[i][j] = pk2(sb[jq * 10 + 2 * j], sb[jq * 10 + 2 * j + 1]);

    const char* wbase = reinterpret_cast<const char*>(sW) + jq * 40;

    for (int k4 = 0; k4 < HIDD / 4; k4++) {
        float4 f[4];
#pragma unroll
        for (int i = 0; i < 4; i++) {
            float4 t = g_hacc[(size_t)nn[i] * 16 + k4];
            t.x = eluf(t.x * inv); t.y = eluf(t.y * inv);
            t.z = eluf(t.z * inv); t.w = eluf(t.w * inv);
            f[i] = t;
        }
#pragma unroll
        for (int q = 0; q < 4; q++) {
            ull hp[4];
            hp[0] = dup2(q == 0 ? f[0].x : q == 1 ? f[0].y : q == 2 ? f[0].z : f[0].w);
            hp[1] = dup2(q == 0 ? f[1].x : q == 1 ? f[1].y : q == 2 ? f[1].z : f[1].w);
            hp[2] = dup2(q == 0 ? f[2].x : q == 1 ? f[2].y : q == 2 ? f[2].z : f[2].w);
            hp[3] = dup2(q == 0 ? f[3].x : q == 1 ? f[3].y : q == 2 ? f[3].z : f[3].w);
            const ull* wrow = reinterpret_cast<const ull*>(wbase + (k4 * 4 + q) * (NC * 4));
#pragma unroll
            for (int j = 0; j < 5; j++) {
                ull wv = wrow[j];
#pragma unroll
                for (int i = 0; i < 4; i++) ffma2(acc[i][j], hp[i], wv);
            }
        }
    }

#pragma unroll
    for (int i = 0; i < 4; i++) {
        float v[10];
#pragma unroll
        for (int j = 0; j < 5; j++) {
            float2 u = upk2(acc[i][j]);
            v[2 * j] = u.x;
            v[2 * j + 1] = u.y;
        }
        float m = -3.4e38f;
#pragma unroll
        for (int j = 0; j < 10; j++) {
            v[j] = (v[j] > 0.f) ? v[j] : (expf(v[j]) - 1.f);
            m = fmaxf(m, v[j]);
        }
        m = fmaxf(m, __shfl_xor_sync(0xffffffffu, m, 1));
        m = fmaxf(m, __shfl_xor_sync(0xffffffffu, m, 2));

        float se = 0.f;
#pragma unroll
        for (int j = 0; j < 10; j++) se += expf(v[j] - m);
        se += __shfl_xor_sync(0xffffffffu, se, 1);
        se += __shfl_xor_sync(0xffffffffu, se, 2);
        float lse = m + logf(se);

        if (av[i]) {
            float* o = out + (size_t)nn[i] * NC + jq * 10;
#pragma unroll
            for (int j = 0; j < 10; j++) o[j] = v[j] - lse;
        }
    }
}

// ---------------- launch ----------------
extern "C" void kernel_launch(void* const* d_in, const int* in_sizes, int n_in,
                              void* d_out, int out_size) {
    const float* x      = (const float*)d_in[0];
    const void*  ei     = (const void*)d_in[1];
    const float* emb_w  = (const float*)d_in[2];
    const float* emb_b  = (const float*)d_in[3];
    const float* Ws     = (const float*)d_in[4];
    const float* attn_a = (const float*)d_in[5];
    const float* out_w  = (const float*)d_in[6];
    const float* out_b  = (const float*)d_in[7];
    float* out          = (float*)d_out;

    (void)in_sizes; (void)n_in; (void)out_size;

    k_detect<<<1, 256>>>((const int*)ei);
    k_prep<<<(EE + 255) / 256, 256>>>(ei);
    k_emb<<<NBG, NTPB>>>(x, emb_w, emb_b);

    for (int l = 0; l < 2; l++) {
        k_gemm_s<<<NBG, NTPB>>>(l, Ws + l * HIDD * HIDD, attn_a + l * 2 * HIDD);
        k_edge<<<EGRID, ETPB>>>(l);
    }

    k_out<<<NBG, NTPB>>>(out_w, out_b, out);
}

// round 9
// speedup vs baseline: 1.2254x; 1.0206x over previous
#include <cuda_runtime.h>

#define NN 100000
#define EE 1600000
#define IND 128
#define HIDD 64
#define NC 40

#define NBG 391               // ceil(NN / 256)
#define NTPB 256
#define EGRID 1184
#define ETPB 256
#define EWPB (ETPB / 32)
#define EWARPS (EGRID * EWPB)
#define SCAN_BLKS 391         // ceil(NN/256)

typedef unsigned long long ull;

// ---------------- device scratch ----------------
__device__ float4 g_h0[NN * 16];     // embedding output
__device__ float4 g_h1[NN * 16];     // layer-0 aggregate (raw)
__device__ float4 g_hacc[NN * 16];   // layer-1 aggregate (raw)
__device__ float4 g_wh[NN * 16];
__device__ float  g_ssrc[NN];
__device__ float  g_sdst[NN];
__device__ float  g_pmax_s[NBG];
__device__ float  g_pmax_d[NBG];
__device__ float  g_psum[EGRID];
__device__ int    g_is64;
// CSR
__device__ int    g_deg[NN];
__device__ int    g_rp[NN];          // block-local exclusive scan
__device__ int    g_btot[SCAN_BLKS];
__device__ int    g_boff[SCAN_BLKS];
__device__ int    g_rowptr[NN + 1];
__device__ int    g_cursor[NN];
__device__ int    g_csrc[EE];

// ---------------- f32x2 helpers ----------------
__device__ __forceinline__ ull pk2(float a, float b) {
    ull r;
    asm("mov.b64 %0, {%1, %2};" : "=l"(r) : "f"(a), "f"(b));
    return r;
}
__device__ __forceinline__ ull dup2(float a) { return pk2(a, a); }
__device__ __forceinline__ float2 upk2(ull v) {
    float2 r;
    asm("mov.b64 {%0, %1}, %2;" : "=f"(r.x), "=f"(r.y) : "l"(v));
    return r;
}
__device__ __forceinline__ void ffma2(ull& acc, ull a, ull b) {
    asm("fma.rn.f32x2 %0, %1, %2, %0;" : "+l"(acc) : "l"(a), "l"(b));
}
__device__ __forceinline__ float eluf(float x) { return x > 0.f ? x : (expf(x) - 1.f); }

// decode edge endpoint (dtype-aware, clamped)
__device__ __forceinline__ void edge_sd(const void* ei, int e, int is64, int& s, int& d) {
    if (is64) {
        s = (int)((const long long*)ei)[e];
        d = (int)((const long long*)ei)[EE + e];
    } else {
        s = ((const int*)ei)[e];
        d = ((const int*)ei)[EE + e];
    }
    s = min(max(s, 0), NN - 1);
    d = min(max(d, 0), NN - 1);
}

// ---------------- dtype detect ----------------
__global__ void k_detect(const int* __restrict__ ei32) {
    int nz = 0;
    for (int i = threadIdx.x; i < 1024; i += blockDim.x)
        if (ei32[2 * i + 1] != 0) nz = 1;
    int cnt = __syncthreads_count(nz);
    if (threadIdx.x == 0) g_is64 = (cnt == 0) ? 1 : 0;
}

// ---------------- CSR build ----------------
__global__ void k_zdeg() {
    int i = blockIdx.x * blockDim.x + threadIdx.x;
    if (i < NN) g_deg[i] = 0;
}

__global__ void k_hist(const void* __restrict__ ei) {
    int is64 = g_is64;
    int e = blockIdx.x * blockDim.x + threadIdx.x;
    if (e >= EE) return;
    int s, d;
    edge_sd(ei, e, is64, s, d);
    atomicAdd(&g_deg[d], 1);
}

__global__ void k_scan1() {
    __shared__ int sm[256];
    int i = blockIdx.x * 256 + threadIdx.x;
    int v = (i < NN) ? g_deg[i] : 0;
    sm[threadIdx.x] = v;
    __syncthreads();
    for (int off = 1; off < 256; off <<= 1) {
        int t = (threadIdx.x >= off) ? sm[threadIdx.x - off] : 0;
        __syncthreads();
        sm[threadIdx.x] += t;
        __syncthreads();
    }
    int incl = sm[threadIdx.x];
    if (i < NN) g_rp[i] = incl - v;
    if (threadIdx.x == 255) g_btot[blockIdx.x] = incl;
}

__global__ void k_scan2() {
    __shared__ int sm[512];
    int tid = threadIdx.x;
    int v = (tid < SCAN_BLKS) ? g_btot[tid] : 0;
    sm[tid] = v;
    __syncthreads();
    for (int off = 1; off < 512; off <<= 1) {
        int t = (tid >= off) ? sm[tid - off] : 0;
        __syncthreads();
        sm[tid] += t;
        __syncthreads();
    }
    if (tid < SCAN_BLKS) g_boff[tid] = sm[tid] - v;
}

__global__ void k_scan3() {
    int i = blockIdx.x * blockDim.x + threadIdx.x;
    if (i < NN) {
        int rp = g_rp[i] + g_boff[i >> 8];
        g_rowptr[i] = rp;
        g_cursor[i] = rp;
    }
    if (i == 0) g_rowptr[NN] = EE;
}

__global__ void k_scat(const void* __restrict__ ei) {
    int is64 = g_is64;
    int e = blockIdx.x * blockDim.x + threadIdx.x;
    if (e >= EE) return;
    int s, d;
    edge_sd(ei, e, is64, s, d);
    int pos = atomicAdd(&g_cursor[d], 1);
    g_csrc[pos] = s;
}

// ---------------- embedding: h0 = x @ emb_w + emb_b ----------------
__global__ void __launch_bounds__(NTPB, 2) k_emb(const float* __restrict__ x,
                                                 const float* __restrict__ w,
                                                 const float* __restrict__ b) {
    __shared__ float4 sW4[IND * HIDD / 4];   // 32 KB
    __shared__ float sb[HIDD];
    int tid = threadIdx.x;
    const float4* wg = reinterpret_cast<const float4*>(w);
    for (int i = tid; i < IND * HIDD / 4; i += NTPB) sW4[i] = wg[i];
    if (tid < HIDD) sb[tid] = b[tid];
    __syncthreads();

    int jq = tid & 3;
    int n0 = blockIdx.x * 256 + (tid >> 2) * 4;
    bool av[4]; int nn[4];
#pragma unroll
    for (int i = 0; i < 4; i++) {
        int n = n0 + i;
        av[i] = (n < NN);
        nn[i] = av[i] ? n : 0;
    }

    ull acc[4][8];
#pragma unroll
    for (int i = 0; i < 4; i++)
#pragma unroll
        for (int j = 0; j < 8; j++)
            acc[i][j] = pk2(sb[jq * 16 + 2 * j], sb[jq * 16 + 2 * j + 1]);

    const char* wbase = reinterpret_cast<const char*>(sW4) + jq * 64;

    for (int k4 = 0; k4 < IND / 4; k4++) {
        float4 f[4];
#pragma unroll
        for (int i = 0; i < 4; i++)
            f[i] = reinterpret_cast<const float4*>(x + (size_t)nn[i] * IND)[k4];
#pragma unroll
        for (int q = 0; q < 4; q++) {
            ull hp[4];
            hp[0] = dup2(q == 0 ? f[0].x : q == 1 ? f[0].y : q == 2 ? f[0].z : f[0].w);
            hp[1] = dup2(q == 0 ? f[1].x : q == 1 ? f[1].y : q == 2 ? f[1].z : f[1].w);
            hp[2] = dup2(q == 0 ? f[2].x : q == 1 ? f[2].y : q == 2 ? f[2].z : f[2].w);
            hp[3] = dup2(q == 0 ? f[3].x : q == 1 ? f[3].y : q == 2 ? f[3].z : f[3].w);
            const ulonglong2* wrow =
                reinterpret_cast<const ulonglong2*>(wbase + (k4 * 4 + q) * (HIDD * 4));
#pragma unroll
            for (int j4 = 0; j4 < 4; j4++) {
                ulonglong2 wv = wrow[j4];
#pragma unroll
                for (int i = 0; i < 4; i++) {
                    ffma2(acc[i][2 * j4], hp[i], wv.x);
                    ffma2(acc[i][2 * j4 + 1], hp[i], wv.y);
                }
            }
        }
    }

#pragma unroll
    for (int i = 0; i < 4; i++) {
        if (!av[i]) continue;
        float4* o = g_h0 + (size_t)nn[i] * 16 + jq * 4;
#pragma unroll
        for (int q = 0; q < 4; q++) {
            float2 u = upk2(acc[i][2 * q]), v = upk2(acc[i][2 * q + 1]);
            o[q] = make_float4(u.x, u.y, v.x, v.y);
        }
    }
}

// ---------------- per-layer GEMM + scores + block max ----------------
__global__ void __launch_bounds__(NTPB, 2) k_gemm_s(int layer,
                                                    const float* __restrict__ W,
                                                    const float* __restrict__ avec) {
    __shared__ float4 sW4[HIDD * HIDD / 4];  // 16 KB
    __shared__ float sa[2 * HIDD];
    __shared__ float sInv;
    int tid = threadIdx.x;
    const float4* wg = reinterpret_cast<const float4*>(W);
    for (int i = tid; i < HIDD * HIDD / 4; i += NTPB) sW4[i] = wg[i];
    if (tid < 2 * HIDD) sa[tid] = avec[tid];

    if (layer) {
        float t = 0.0f;
        for (int i = tid; i < EGRID; i += NTPB) t += g_psum[i];
#pragma unroll
        for (int o = 16; o; o >>= 1) t += __shfl_xor_sync(0xffffffffu, t, o);
        __shared__ float sm[8];
        if ((tid & 31) == 0) sm[tid >> 5] = t;
        __syncthreads();
        if (tid == 0) {
            float s = 0.0f;
            for (int i = 0; i < 8; i++) s += sm[i];
            sInv = (s > 0.0f) ? (1.0f / s) : 0.0f;
        }
    }
    __syncthreads();
    float inv = layer ? sInv : 1.0f;

    int jq = tid & 3;
    int n0 = blockIdx.x * 256 + (tid >> 2) * 4;
    bool av[4]; int nn[4];
#pragma unroll
    for (int i = 0; i < 4; i++) {
        int n = n0 + i;
        av[i] = (n < NN);
        nn[i] = av[i] ? n : 0;
    }

    ull acc[4][8];
#pragma unroll
    for (int i = 0; i < 4; i++)
#pragma unroll
        for (int j = 0; j < 8; j++) acc[i][j] = 0ull;

    const float4* hb = layer ? g_h1 : g_h0;
    const char* wbase = reinterpret_cast<const char*>(sW4) + jq * 64;

    for (int k4 = 0; k4 < HIDD / 4; k4++) {
        float4 f[4];
#pragma unroll
        for (int i = 0; i < 4; i++) {
            float4 t = hb[(size_t)nn[i] * 16 + k4];
            if (layer) {
                t.x = eluf(t.x * inv); t.y = eluf(t.y * inv);
                t.z = eluf(t.z * inv); t.w = eluf(t.w * inv);
            }
            f[i] = t;
        }
#pragma unroll
        for (int q = 0; q < 4; q++) {
            ull hp[4];
            hp[0] = dup2(q == 0 ? f[0].x : q == 1 ? f[0].y : q == 2 ? f[0].z : f[0].w);
            hp[1] = dup2(q == 0 ? f[1].x : q == 1 ? f[1].y : q == 2 ? f[1].z : f[1].w);
            hp[2] = dup2(q == 0 ? f[2].x : q == 1 ? f[2].y : q == 2 ? f[2].z : f[2].w);
            hp[3] = dup2(q == 0 ? f[3].x : q == 1 ? f[3].y : q == 2 ? f[3].z : f[3].w);
            const ulonglong2* wrow =
                reinterpret_cast<const ulonglong2*>(wbase + (k4 * 4 + q) * (HIDD * 4));
#pragma unroll
            for (int j4 = 0; j4 < 4; j4++) {
                ulonglong2 wv = wrow[j4];
#pragma unroll
                for (int i = 0; i < 4; i++) {
                    ffma2(acc[i][2 * j4], hp[i], wv.x);
                    ffma2(acc[i][2 * j4 + 1], hp[i], wv.y);
                }
            }
        }
    }

    float ss[4], sd[4];
#pragma unroll
    for (int i = 0; i < 4; i++) {
        float s1 = 0.f, s2 = 0.f;
#pragma unroll
        for (int j = 0; j < 8; j++) {
            float2 v = upk2(acc[i][j]);
            s1 += v.x * sa[jq * 16 + 2 * j] + v.y * sa[jq * 16 + 2 * j + 1];
            s2 += v.x * sa[HIDD + jq * 16 + 2 * j] + v.y * sa[HIDD + jq * 16 + 2 * j + 1];
        }
        s1 += __shfl_xor_sync(0xffffffffu, s1, 1);
        s1 += __shfl_xor_sync(0xffffffffu, s1, 2);
        s2 += __shfl_xor_sync(0xffffffffu, s2, 1);
        s2 += __shfl_xor_sync(0xffffffffu, s2, 2);
        ss[i] = s1; sd[i] = s2;
    }

#pragma unroll
    for (int i = 0; i < 4; i++) {
        if (!av[i]) continue;
        if (jq == 0) { g_ssrc[nn[i]] = ss[i]; g_sdst[nn[i]] = sd[i]; }
        float4* wout = g_wh + (size_t)nn[i] * 16 + jq * 4;
#pragma unroll
        for (int q = 0; q < 4; q++) {
            float2 u = upk2(acc[i][2 * q]), v = upk2(acc[i][2 * q + 1]);
            wout[q] = make_float4(u.x, u.y, v.x, v.y);
        }
    }

    float ms = -3.4e38f, md = -3.4e38f;
#pragma unroll
    for (int i = 0; i < 4; i++) {
        if (av[i]) { ms = fmaxf(ms, ss[i]); md = fmaxf(md, sd[i]); }
    }
#pragma unroll
    for (int o = 16; o; o >>= 1) {
        ms = fmaxf(ms, __shfl_xor_sync(0xffffffffu, ms, o));
        md = fmaxf(md, __shfl_xor_sync(0xffffffffu, md, o));
    }
    __shared__ float sms[8], smd[8];
    if ((tid & 31) == 0) { sms[tid >> 5] = ms; smd[tid >> 5] = md; }
    __syncthreads();
    if (tid == 0) {
        float a = sms[0], b = smd[0];
        for (int i = 1; i < 8; i++) { a = fmaxf(a, sms[i]); b = fmaxf(b, smd[i]); }
        g_pmax_s[blockIdx.x] = a;
        g_pmax_d[blockIdx.x] = b;
    }
}

// ---------------- CSR aggregation: warp per dst, no atomics ----------------
__global__ void __launch_bounds__(ETPB) k_aggr(int layer) {
    __shared__ float sB;
    {
        float a = -3.4e38f, b = -3.4e38f;
        for (int i = threadIdx.x; i < NBG; i += ETPB) {
            a = fmaxf(a, g_pmax_s[i]);
            b = fmaxf(b, g_pmax_d[i]);
        }
#pragma unroll
        for (int o = 16; o; o >>= 1) {
            a = fmaxf(a, __shfl_xor_sync(0xffffffffu, a, o));
            b = fmaxf(b, __shfl_xor_sync(0xffffffffu, b, o));
        }
        __shared__ float ra[EWPB], rb[EWPB];
        if ((threadIdx.x & 31) == 0) { ra[threadIdx.x >> 5] = a; rb[threadIdx.x >> 5] = b; }
        __syncthreads();
        if (threadIdx.x == 0) {
            float ma = ra[0], mb = rb[0];
            for (int i = 1; i < EWPB; i++) { ma = fmaxf(ma, ra[i]); mb = fmaxf(mb, rb[i]); }
            sB = ma + mb;
        }
        __syncthreads();
    }
    const float B = sB;

    int lane = threadIdx.x & 31;
    int wid = threadIdx.x >> 5;

    const float* whf = reinterpret_cast<const float*>(g_wh);
    float* accf = reinterpret_cast<float*>(layer ? g_hacc : g_h1);

    float psum = 0.0f;
    for (int d = blockIdx.x * EWPB + wid; d < NN; d += EWARPS) {
        int beg = g_rowptr[d];
        int end = g_rowptr[d + 1];
        float sdd = g_sdst[d];
        float a0 = 0.f, a1 = 0.f, b0 = 0.f, b1 = 0.f;

        for (int c = beg; c < end; c += 32) {
            int e = c + lane;
            int s = 0; float p = 0.f;
            if (e < end) {
                s = g_csrc[e];
                float sc = g_ssrc[s] + sdd;
                if (sc > 0.f) p = expf(sc - B);
            }
            psum += p;

            unsigned act = __ballot_sync(0xffffffffu, p != 0.f);
            while (act) {
                int j0 = __ffs(act) - 1; act &= act - 1;
                int s0 = __shfl_sync(0xffffffffu, s, j0);
                float p0 = __shfl_sync(0xffffffffu, p, j0);
                if (act) {
                    int j1 = __ffs(act) - 1; act &= act - 1;
                    int s1 = __shfl_sync(0xffffffffu, s, j1);
                    float p1 = __shfl_sync(0xffffffffu, p, j1);
                    const float* w0 = whf + (size_t)s0 * HIDD;
                    const float* w1 = whf + (size_t)s1 * HIDD;
                    float x00 = w0[lane], x01 = w0[32 + lane];
                    float x10 = w1[lane], x11 = w1[32 + lane];
                    a0 += p0 * x00; a1 += p0 * x01;
                    b0 += p1 * x10; b1 += p1 * x11;
                } else {
                    const float* w0 = whf + (size_t)s0 * HIDD;
                    a0 += p0 * w0[lane];
                    a1 += p0 * w0[32 + lane];
                }
            }
        }

        accf[(size_t)d * HIDD + lane] = a0 + b0;
        accf[(size_t)d * HIDD + 32 + lane] = a1 + b1;
    }

#pragma unroll
    for (int o = 16; o; o >>= 1) psum += __shfl_xor_sync(0xffffffffu, psum, o);
    __shared__ float sm2[EWPB];
    if (lane == 0) sm2[wid] = psum;
    __syncthreads();
    if (threadIdx.x == 0) {
        float t = 0.0f;
        for (int i = 0; i < EWPB; i++) t += sm2[i];
        g_psum[blockIdx.x] = t;
    }
}

// ---------------- output head: transform + GEMM + ELU + log_softmax ----------------
__global__ void __launch_bounds__(NTPB, 2) k_out(const float* __restrict__ W,
                                                 const float* __restrict__ b,
                                                 float* __restrict__ out) {
    __shared__ __align__(16) float sW[HIDD * NC];   // 10 KB
    __shared__ float sb[NC];
    __shared__ float sInv;
    int tid = threadIdx.x;
    for (int i = tid; i < HIDD * NC; i += NTPB) sW[i] = W[i];
    if (tid < NC) sb[tid] = b[tid];
    {
        float t = 0.0f;
        for (int i = tid; i < EGRID; i += NTPB) t += g_psum[i];
#pragma unroll
        for (int o = 16; o; o >>= 1) t += __shfl_xor_sync(0xffffffffu, t, o);
        __shared__ float sm[8];
        if ((tid & 31) == 0) sm[tid >> 5] = t;
        __syncthreads();
        if (tid == 0) {
            float s = 0.0f;
            for (int i = 0; i < 8; i++) s += sm[i];
            sInv = (s > 0.0f) ? (1.0f / s) : 0.0f;
        }
    }
    __syncthreads();
    float inv = sInv;

    int jq = tid & 3;
    int n0 = blockIdx.x * 256 + (tid >> 2) * 4;
    bool av[4]; int nn[4];
#pragma unroll
    for (int i = 0; i < 4; i++) {
        int n = n0 + i;
        av[i] = (n < NN);
        nn[i] = av[i] ? n : 0;
    }

    ull acc[4][5];
#pragma unroll
    for (int i = 0; i < 4; i++)
#pragma unroll
        for (int j = 0; j < 5; j++)
            acc[i][j] = pk2(sb[jq * 10 + 2 * j], sb[jq * 10 + 2 * j + 1]);

    const char* wbase = reinterpret_cast<const char*>(sW) + jq * 40;

    for (int k4 = 0; k4 < HIDD / 4; k4++) {
        float4 f[4];
#pragma unroll
        for (int i = 0; i < 4; i++) {
            float4 t = g_hacc[(size_t)nn[i] * 16 + k4];
            t.x = eluf(t.x * inv); t.y = eluf(t.y * inv);
            t.z = eluf(t.z * inv); t.w = eluf(t.w * inv);
            f[i] = t;
        }
#pragma unroll
        for (int q = 0; q < 4; q++) {
            ull hp[4];
            hp[0] = dup2(q == 0 ? f[0].x : q == 1 ? f[0].y : q == 2 ? f[0].z : f[0].w);
            hp[1] = dup2(q == 0 ? f[1].x : q == 1 ? f[1].y : q == 2 ? f[1].z : f[1].w);
            hp[2] = dup2(q == 0 ? f[2].x : q == 1 ? f[2].y : q == 2 ? f[2].z : f[2].w);
            hp[3] = dup2(q == 0 ? f[3].x : q == 1 ? f[3].y : q == 2 ? f[3].z : f[3].w);
            const ull* wrow = reinterpret_cast<const ull*>(wbase + (k4 * 4 + q) * (NC * 4));
#pragma unroll
            for (int j = 0; j < 5; j++) {
                ull wv = wrow[j];
#pragma unroll
                for (int i = 0; i < 4; i++) ffma2(acc[i][j], hp[i], wv);
            }
        }
    }

#pragma unroll
    for (int i = 0; i < 4; i++) {
        float v[10];
#pragma unroll
        for (int j = 0; j < 5; j++) {
            float2 u = upk2(acc[i][j]);
            v[2 * j] = u.x;
            v[2 * j + 1] = u.y;
        }
        float m = -3.4e38f;
#pragma unroll
        for (int j = 0; j < 10; j++) {
            v[j] = (v[j] > 0.f) ? v[j] : (expf(v[j]) - 1.f);
            m = fmaxf(m, v[j]);
        }
        m = fmaxf(m, __shfl_xor_sync(0xffffffffu, m, 1));
        m = fmaxf(m, __shfl_xor_sync(0xffffffffu, m, 2));

        float se = 0.f;
#pragma unroll
        for (int j = 0; j < 10; j++) se += expf(v[j] - m);
        se += __shfl_xor_sync(0xffffffffu, se, 1);
        se += __shfl_xor_sync(0xffffffffu, se, 2);
        float lse = m + logf(se);

        if (av[i]) {
            float* o = out + (size_t)nn[i] * NC + jq * 10;
#pragma unroll
            for (int j = 0; j < 10; j++) o[j] = v[j] - lse;
        }
    }
}

// ---------------- launch ----------------
extern "C" void kernel_launch(void* const* d_in, const int* in_sizes, int n_in,
                              void* d_out, int out_size) {
    const float* x      = (const float*)d_in[0];
    const void*  ei     = (const void*)d_in[1];
    const float* emb_w  = (const float*)d_in[2];
    const float* emb_b  = (const float*)d_in[3];
    const float* Ws     = (const float*)d_in[4];
    const float* attn_a = (const float*)d_in[5];
    const float* out_w  = (const float*)d_in[6];
    const float* out_b  = (const float*)d_in[7];
    float* out          = (float*)d_out;

    (void)in_sizes; (void)n_in; (void)out_size;

    const int EB = (EE + 255) / 256;
    const int NB = (NN + 255) / 256;

    k_detect<<<1, 256>>>((const int*)ei);
    // CSR build (every launch; deterministic inputs -> same structure)
    k_zdeg<<<NB, 256>>>();
    k_hist<<<EB, 256>>>(ei);
    k_scan1<<<SCAN_BLKS, 256>>>();
    k_scan2<<<1, 512>>>();
    k_scan3<<<NB, 256>>>();
    k_scat<<<EB, 256>>>(ei);

    k_emb<<<NBG, NTPB>>>(x, emb_w, emb_b);

    for (int l = 0; l < 2; l++) {
        k_gemm_s<<<NBG, NTPB>>>(l, Ws + l * HIDD * HIDD, attn_a + l * 2 * HIDD);
        k_aggr<<<EGRID, ETPB>>>(l);
    }

    k_out<<<NBG, NTPB>>>(out_w, out_b, out);
}